// round 14
// baseline (speedup 1.0000x reference)
#include <cuda_runtime.h>
#include <cuda_fp16.h>
#include <cstdint>

#define NB 1024
#define NT 256
#define NE 300
#define LOG2E 1.4426950408889634f
#define INVL2E 0.6931471805599453f
#define NTH 512
#define RH4 64        // rows per quarter
#define CH 4          // online-softmax chunk (registers per column; occ-3 budget)

#define MG_STRIDE 260  // words; k_Gv load-once row stride

// ---------------- static device precompute (no allocations allowed) ----------------
__device__ float g_M[NT * NT];       // M[t][f] = sum_e TE[e][t] * Wf[f][e]
__device__ float g_G2[NT * NT];      // (M M^T) * log2(e)   (symmetric)
__device__ float g_v2[NT];           // (M b_f) * log2(e)
__device__ float g_c2;               // (b_f . b_f) * log2(e)

__device__ __forceinline__ float fast_exp2(float x) {
    float y; asm("ex2.approx.f32 %0, %1;" : "=f"(y) : "f"(x)); return y;
}
__device__ __forceinline__ float fast_lg2(float x) {
    float y; asm("lg2.approx.f32 %0, %1;" : "=f"(y) : "f"(x)); return y;
}

// ---------------- k_M: 16x16 tiles, grid 256, double-buffered (R10 best) ----------
__global__ void __launch_bounds__(256) k_M(const float* __restrict__ te,
                                           const float* __restrict__ wf) {
    __shared__ float TEs[2][32][17];   // [buf][e_l][t_l]
    __shared__ float WFs[2][16][33];   // [buf][f_l][e_l]
    int lid = threadIdx.x;
    int tx = lid & 15;                 // f_l
    int ty = lid >> 4;                 // t_l
    int t0 = blockIdx.y * 16, f0 = blockIdx.x * 16;
    int te_el = lid >> 4, te_tl = lid & 15;
    int wf_el = lid & 31, wf_fl = lid >> 5;
    const int NTILE = (NE + 31) / 32;  // 10

    float pT0, pT1, pW0, pW1;
    {
        int e1 = te_el;
        pT0 = (e1 < NE) ? te[e1 * NT + t0 + te_tl] : 0.f;
        int e2 = e1 + 16;
        pT1 = (e2 < NE) ? te[e2 * NT + t0 + te_tl] : 0.f;
        int e = wf_el;
        pW0 = (e < NE) ? wf[(f0 + wf_fl) * NE + e] : 0.f;
        pW1 = (e < NE) ? wf[(f0 + wf_fl + 8) * NE + e] : 0.f;
    }
    TEs[0][te_el][te_tl] = pT0; TEs[0][te_el + 16][te_tl] = pT1;
    WFs[0][wf_fl][wf_el] = pW0; WFs[0][wf_fl + 8][wf_el] = pW1;
    __syncthreads();

    float acc = 0.f;
    for (int it = 0; it < NTILE; it++) {
        int cur = it & 1;
        if (it + 1 < NTILE) {
            int e0 = (it + 1) * 32;
            int e1 = e0 + te_el;
            pT0 = (e1 < NE) ? te[e1 * NT + t0 + te_tl] : 0.f;
            int e2 = e1 + 16;
            pT1 = (e2 < NE) ? te[e2 * NT + t0 + te_tl] : 0.f;
            int e = e0 + wf_el;
            pW0 = (e < NE) ? wf[(f0 + wf_fl) * NE + e] : 0.f;
            pW1 = (e < NE) ? wf[(f0 + wf_fl + 8) * NE + e] : 0.f;
        }
#pragma unroll
        for (int k = 0; k < 32; k++)
            acc = fmaf(TEs[cur][k][ty], WFs[cur][tx][k], acc);
        if (it + 1 < NTILE) {
            TEs[cur ^ 1][te_el][te_tl] = pT0; TEs[cur ^ 1][te_el + 16][te_tl] = pT1;
            WFs[cur ^ 1][wf_fl][wf_el] = pW0; WFs[cur ^ 1][wf_fl + 8][wf_el] = pW1;
        }
        __syncthreads();
    }
    g_M[(t0 + ty) * NT + f0 + tx] = acc;
}

// ---------------- k_Gv: load-once 16x16 tile (R13 variant); + v2 + c2 -------------
__global__ void __launch_bounds__(256) k_Gv(const float* __restrict__ bf) {
    __shared__ float As[16][MG_STRIDE];    // [i_l][k]
    __shared__ float Bs[16][MG_STRIDE];    // [j_l][k]
    __shared__ float bshf[NT];
    int lid = threadIdx.x;
    int tx = lid & 15;                 // j_l
    int ty = lid >> 4;                 // i_l
    int i0 = blockIdx.y * 16, j0 = blockIdx.x * 16;
    int wid = lid >> 5, lane = lid & 31;

    bshf[lid] = bf[lid];
    for (int r = wid * 2; r < wid * 2 + 2; r++) {
        const float* arow = g_M + (size_t)(i0 + r) * NT;
        const float* brow = g_M + (size_t)(j0 + r) * NT;
        for (int k = lane; k < NT; k += 32) {
            As[r][k] = arow[k];
            Bs[r][k] = brow[k];
        }
    }
    __syncthreads();

    const float4* arow4 = (const float4*)As[ty];
    const float4* brow4 = (const float4*)Bs[tx];
    float a0 = 0.f, a1 = 0.f, a2 = 0.f, a3 = 0.f;
#pragma unroll 8
    for (int q = 0; q < NT / 4; q++) {
        float4 av = arow4[q];
        float4 bv = brow4[q];
        a0 = fmaf(av.x, bv.x, a0);
        a1 = fmaf(av.y, bv.y, a1);
        a2 = fmaf(av.z, bv.z, a2);
        a3 = fmaf(av.w, bv.w, a3);
    }
    g_G2[(i0 + ty) * NT + j0 + tx] = ((a0 + a1) + (a2 + a3)) * LOG2E;

    if (blockIdx.y == 0 && ty == 0) {
        const float4* bf4 = (const float4*)bshf;
        float v0 = 0.f, v1 = 0.f, v2a = 0.f, v3 = 0.f;
#pragma unroll 8
        for (int q = 0; q < NT / 4; q++) {
            float4 bv = brow4[q];
            float4 fv = bf4[q];
            v0 = fmaf(bv.x, fv.x, v0);
            v1 = fmaf(bv.y, fv.y, v1);
            v2a = fmaf(bv.z, fv.z, v2a);
            v3 = fmaf(bv.w, fv.w, v3);
        }
        g_v2[j0 + tx] = ((v0 + v1) + (v2a + v3)) * LOG2E;
        if (blockIdx.x == 0 && tx == 0) {
            float c0 = 0.f;
            for (int k = 0; k < NT; k++) c0 = fmaf(bshf[k], bshf[k], c0);
            g_c2 = c0 * LOG2E;
        }
    }
}

// ---------------- fused per-batch kernel — occupancy 3 (48 warps/SM) --------------
// a'[r][c] = (w_c*r_r)*G2[r][c] + p2[r]   (log2 domain; per-column const cancels)
// Thread owns columns c0=2cp, c1=2cp+1 (LDG.64 on G2) and rows [64h, 64h+64).
__global__ void __launch_bounds__(NTH, 3) k_fused(const float* __restrict__ req,
                                                  const float* __restrict__ wsdl,
                                                  float* __restrict__ out) {
    __shared__ float2 rp[NT];          // (r, r*v2) per row
    __shared__ float2 bq[NT];          // (w_c, qcz_c) per column
    __shared__ float  us[NT];
    __shared__ float2 mh2[4 * 128], Zh2[4 * 128], yh2[4 * 128];
    __shared__ float2 sh2[4 * 128], zh2[4 * 128];
    __shared__ float red[16 * 6];

    int tid = threadIdx.x;
    int cp = tid & 127;
    int h = tid >> 7;
    int b = blockIdx.x;

    float2 rr = ((const float2*)req)[b * 128 + cp];
    float2 ww = ((const float2*)wsdl)[b * 128 + cp];
    float2 vv = ((const float2*)g_v2)[cp];
    float p20 = rr.x * vv.x, p21 = rr.y * vv.y;
    if (h == 0) {
        rp[2 * cp]     = make_float2(rr.x, p20);
        rp[2 * cp + 1] = make_float2(rr.y, p21);
    }
    __syncthreads();

    const float2* G2v = (const float2*)g_G2;   // row r: G2v[r*128 + cp]
    int rbase = h * RH4;

    // ---- pass A: online column max + Z + y over rows [rbase, rbase+64) ----
    float m0 = -1e30f, m1 = -1e30f, Z0 = 0.f, Z1 = 0.f, y0 = 0.f, y1 = 0.f;
#pragma unroll
    for (int k = 0; k < RH4 / CH; k++) {
        float a0[CH], a1[CH];
        float cm0 = -1e30f, cm1 = -1e30f;
#pragma unroll
        for (int i = 0; i < CH; i++) {
            int r = rbase + k * CH + i;
            float2 g = G2v[r * 128 + cp];
            float2 q = rp[r];                      // broadcast
            a0[i] = fmaf(ww.x * q.x, g.x, q.y);
            a1[i] = fmaf(ww.y * q.x, g.y, q.y);
            y0 = fmaf(g.x, q.x, y0);
            y1 = fmaf(g.y, q.x, y1);
            cm0 = fmaxf(cm0, a0[i]);
            cm1 = fmaxf(cm1, a1[i]);
        }
        float mn0 = fmaxf(m0, cm0), mn1 = fmaxf(m1, cm1);
        Z0 *= fast_exp2(m0 - mn0);   // first chunk: 0 * 2^-huge = 0
        Z1 *= fast_exp2(m1 - mn1);
        m0 = mn0; m1 = mn1;
#pragma unroll
        for (int i = 0; i < CH; i++) {
            Z0 += fast_exp2(a0[i] - m0);
            Z1 += fast_exp2(a1[i] - m1);
        }
    }
    mh2[h * 128 + cp] = make_float2(m0, m1);
    Zh2[h * 128 + cp] = make_float2(Z0, Z1);
    yh2[h * 128 + cp] = make_float2(y0, y1);
    __syncthreads();

    // ---- combine column stats (h==0) -> bq ----
    if (h == 0) {
        float2 ma = mh2[cp], mb = mh2[128 + cp], mc = mh2[256 + cp], md = mh2[384 + cp];
        float mx0 = fmaxf(fmaxf(ma.x, mb.x), fmaxf(mc.x, md.x));
        float mx1 = fmaxf(fmaxf(ma.y, mb.y), fmaxf(mc.y, md.y));
        float2 za = Zh2[cp], zb = Zh2[128 + cp], zc = Zh2[256 + cp], zd = Zh2[384 + cp];
        float Zt0 = za.x * fast_exp2(ma.x - mx0) + zb.x * fast_exp2(mb.x - mx0)
                  + zc.x * fast_exp2(mc.x - mx0) + zd.x * fast_exp2(md.x - mx0);
        float Zt1 = za.y * fast_exp2(ma.y - mx1) + zb.y * fast_exp2(mb.y - mx1)
                  + zc.y * fast_exp2(mc.y - mx1) + zd.y * fast_exp2(md.y - mx1);
        bq[2 * cp]     = make_float2(ww.x, -mx0 - fast_lg2(Zt0));
        bq[2 * cp + 1] = make_float2(ww.y, -mx1 - fast_lg2(Zt1));
    }
    __syncthreads();

    // ---- pass B: s_j over columns cc in [rbase, rbase+64), j = c0,c1 ----
    {
        float s0 = 0.f, s1 = 0.f;
#pragma unroll 16
        for (int cc = rbase; cc < rbase + RH4; cc++) {
            float2 g = G2v[cc * 128 + cp];         // G2[cc][c0], G2[cc][c1]
            float2 t = bq[cc];                     // broadcast
            s0 += fast_exp2(fmaf(t.x * rr.x, g.x, t.y));
            s1 += fast_exp2(fmaf(t.x * rr.y, g.y, t.y));
        }
        sh2[h * 128 + cp] = make_float2(s0, s1);
    }
    __syncthreads();

    // ---- u (h==0 only) ----
    float st0 = 0.f, st1 = 0.f, u0 = 0.f, u1 = 0.f;
    if (h == 0) {
        float2 sa = sh2[cp], sb = sh2[128 + cp], sc = sh2[256 + cp], sd = sh2[384 + cp];
        st0 = ((sa.x + sb.x) + (sc.x + sd.x)) * fast_exp2(p20);
        st1 = ((sa.y + sb.y) + (sc.y + sd.y)) * fast_exp2(p21);
        u0 = st0 * rr.x;
        u1 = st1 * rr.y;
        us[2 * cp] = u0;
        us[2 * cp + 1] = u1;
    }
    __syncthreads();

    // ---- pass C: z = G*u partials ----
    {
        float z0 = 0.f, z1 = 0.f;
#pragma unroll 16
        for (int r = rbase; r < rbase + RH4; r++) {
            float2 g = G2v[r * 128 + cp];
            float uu = us[r];                      // broadcast
            z0 = fmaf(g.x, uu, z0);
            z1 = fmaf(g.y, uu, z1);
        }
        zh2[h * 128 + cp] = make_float2(z0, z1);
    }
    __syncthreads();

    // ---- reductions (h==0 contributes): T0=r.y T1=u.y T2=u.z T3=r.v T4=u.v T5=S --
    float t0 = 0.f, t1 = 0.f, t2 = 0.f, t3 = 0.f, t4 = 0.f, t5 = 0.f;
    if (h == 0) {
        float2 ya = yh2[cp], yb = yh2[128 + cp], yc = yh2[256 + cp], yd = yh2[384 + cp];
        float y0t = (ya.x + yb.x) + (yc.x + yd.x);
        float y1t = (ya.y + yb.y) + (yc.y + yd.y);
        float2 za = zh2[cp], zb = zh2[128 + cp], zc = zh2[256 + cp], zd = zh2[384 + cp];
        float z0t = (za.x + zb.x) + (zc.x + zd.x);
        float z1t = (za.y + zb.y) + (zc.y + zd.y);
        t0 = rr.x * y0t + rr.y * y1t;
        t1 = u0 * y0t + u1 * y1t;
        t2 = u0 * z0t + u1 * z1t;
        t3 = rr.x * vv.x + rr.y * vv.y;
        t4 = u0 * vv.x + u1 * vv.y;
        t5 = st0 + st1;
    }
#pragma unroll
    for (int o = 16; o; o >>= 1) {
        t0 += __shfl_down_sync(0xffffffffu, t0, o);
        t1 += __shfl_down_sync(0xffffffffu, t1, o);
        t2 += __shfl_down_sync(0xffffffffu, t2, o);
        t3 += __shfl_down_sync(0xffffffffu, t3, o);
        t4 += __shfl_down_sync(0xffffffffu, t4, o);
        t5 += __shfl_down_sync(0xffffffffu, t5, o);
    }
    if ((tid & 31) == 0) {
        int w = tid >> 5;
        red[w * 6 + 0] = t0; red[w * 6 + 1] = t1; red[w * 6 + 2] = t2;
        red[w * 6 + 3] = t3; red[w * 6 + 4] = t4; red[w * 6 + 5] = t5;
    }
    __syncthreads();
    if (tid == 0) {
        float T0 = 0, T1 = 0, T2 = 0, T3 = 0, T4 = 0, S = 0;
#pragma unroll
        for (int w = 0; w < 4; w++) {             // only warps 0-3 contribute (h==0)
            T0 += red[w * 6 + 0]; T1 += red[w * 6 + 1]; T2 += red[w * 6 + 2];
            T3 += red[w * 6 + 3]; T4 += red[w * 6 + 4]; S  += red[w * 6 + 5];
        }
        float c_un = g_c2 * INVL2E;
        const float Tf = (float)NT;
        float num = (T1 + S * T3 + Tf * T4) * INVL2E + Tf * S * c_un;
        float n1s = (T0 + 2.0f * Tf * T3) * INVL2E + Tf * Tf * c_un;
        float n2s = (T2 + 2.0f * S * T4) * INVL2E + S * S * c_un;
        float denom = fmaxf(sqrtf(n1s) * sqrtf(n2s), 1e-8f * Tf * Tf);
        out[b] = 3.0f * num / denom;
    }
}

extern "C" void kernel_launch(void* const* d_in, const int* in_sizes, int n_in,
                              void* d_out, int out_size) {
    const float* req  = (const float*)d_in[0];   // [B,T]
    const float* wsdl = (const float*)d_in[1];   // [B,T]
    const float* te   = (const float*)d_in[2];   // [E,T]
    const float* wf   = (const float*)d_in[3];   // [T,E]
    const float* bf   = (const float*)d_in[4];   // [T]
    float* out = (float*)d_out;                  // [B]

    dim3 grd(16, 16);
    k_M<<<grd, 256>>>(te, wf);
    k_Gv<<<grd, 256>>>(bf);
    k_fused<<<NB, NTH>>>(req, wsdl, out);
}

// round 15
// speedup vs baseline: 1.0789x; 1.0789x over previous
#include <cuda_runtime.h>
#include <cuda_fp16.h>
#include <cstdint>

#define NB 1024
#define NT 256
#define NE 300
#define LOG2E 1.4426950408889634f
#define INVL2E 0.6931471805599453f
#define NTH 512
#define RH4 64        // rows per quarter
#define CH 8          // online-softmax chunk (registers per column)

#define MG_STRIDE 260  // words; k_Gv load-once row stride (260%32=4)

// ---------------- static device precompute (no allocations allowed) ----------------
__device__ float g_M[NT * NT];       // M[t][f] = sum_e TE[e][t] * Wf[f][e]
__device__ float g_G2[NT * NT];      // (M M^T) * log2(e)   (symmetric)
__device__ float g_v2[NT];           // (M b_f) * log2(e)
__device__ float g_c2;               // (b_f . b_f) * log2(e)

__device__ __forceinline__ float fast_exp2(float x) {
    float y; asm("ex2.approx.f32 %0, %1;" : "=f"(y) : "f"(x)); return y;
}
__device__ __forceinline__ float fast_lg2(float x) {
    float y; asm("lg2.approx.f32 %0, %1;" : "=f"(y) : "f"(x)); return y;
}

// ---------------- k_M: 16x16 tiles, grid 256, double-buffered (measured best) -----
__global__ void __launch_bounds__(256) k_M(const float* __restrict__ te,
                                           const float* __restrict__ wf) {
    __shared__ float TEs[2][32][17];   // [buf][e_l][t_l]
    __shared__ float WFs[2][16][33];   // [buf][f_l][e_l]
    int lid = threadIdx.x;
    int tx = lid & 15;                 // f_l
    int ty = lid >> 4;                 // t_l
    int t0 = blockIdx.y * 16, f0 = blockIdx.x * 16;
    int te_el = lid >> 4, te_tl = lid & 15;
    int wf_el = lid & 31, wf_fl = lid >> 5;
    const int NTILE = (NE + 31) / 32;  // 10

    float pT0, pT1, pW0, pW1;
    {
        int e1 = te_el;
        pT0 = (e1 < NE) ? te[e1 * NT + t0 + te_tl] : 0.f;
        int e2 = e1 + 16;
        pT1 = (e2 < NE) ? te[e2 * NT + t0 + te_tl] : 0.f;
        int e = wf_el;
        pW0 = (e < NE) ? wf[(f0 + wf_fl) * NE + e] : 0.f;
        pW1 = (e < NE) ? wf[(f0 + wf_fl + 8) * NE + e] : 0.f;
    }
    TEs[0][te_el][te_tl] = pT0; TEs[0][te_el + 16][te_tl] = pT1;
    WFs[0][wf_fl][wf_el] = pW0; WFs[0][wf_fl + 8][wf_el] = pW1;
    __syncthreads();

    float acc = 0.f;
    for (int it = 0; it < NTILE; it++) {
        int cur = it & 1;
        if (it + 1 < NTILE) {
            int e0 = (it + 1) * 32;
            int e1 = e0 + te_el;
            pT0 = (e1 < NE) ? te[e1 * NT + t0 + te_tl] : 0.f;
            int e2 = e1 + 16;
            pT1 = (e2 < NE) ? te[e2 * NT + t0 + te_tl] : 0.f;
            int e = e0 + wf_el;
            pW0 = (e < NE) ? wf[(f0 + wf_fl) * NE + e] : 0.f;
            pW1 = (e < NE) ? wf[(f0 + wf_fl + 8) * NE + e] : 0.f;
        }
#pragma unroll
        for (int k = 0; k < 32; k++)
            acc = fmaf(TEs[cur][k][ty], WFs[cur][tx][k], acc);
        if (it + 1 < NTILE) {
            TEs[cur ^ 1][te_el][te_tl] = pT0; TEs[cur ^ 1][te_el + 16][te_tl] = pT1;
            WFs[cur ^ 1][wf_fl][wf_el] = pW0; WFs[cur ^ 1][wf_fl + 8][wf_el] = pW1;
        }
        __syncthreads();
    }
    g_M[(t0 + ty) * NT + f0 + tx] = acc;
}

// ---------------- k_Gv: load-once 16x16 tile (measured best); + v2 + c2 -----------
__global__ void __launch_bounds__(256) k_Gv(const float* __restrict__ bf) {
    __shared__ float As[16][MG_STRIDE];    // [i_l][k]
    __shared__ float Bs[16][MG_STRIDE];    // [j_l][k]
    __shared__ float bshf[NT];
    int lid = threadIdx.x;
    int tx = lid & 15;                 // j_l
    int ty = lid >> 4;                 // i_l
    int i0 = blockIdx.y * 16, j0 = blockIdx.x * 16;
    int wid = lid >> 5, lane = lid & 31;

    bshf[lid] = bf[lid];
    for (int r = wid * 2; r < wid * 2 + 2; r++) {
        const float* arow = g_M + (size_t)(i0 + r) * NT;
        const float* brow = g_M + (size_t)(j0 + r) * NT;
        for (int k = lane; k < NT; k += 32) {
            As[r][k] = arow[k];
            Bs[r][k] = brow[k];
        }
    }
    __syncthreads();

    const float4* arow4 = (const float4*)As[ty];
    const float4* brow4 = (const float4*)Bs[tx];
    float a0 = 0.f, a1 = 0.f, a2 = 0.f, a3 = 0.f;
#pragma unroll 8
    for (int q = 0; q < NT / 4; q++) {
        float4 av = arow4[q];
        float4 bv = brow4[q];
        a0 = fmaf(av.x, bv.x, a0);
        a1 = fmaf(av.y, bv.y, a1);
        a2 = fmaf(av.z, bv.z, a2);
        a3 = fmaf(av.w, bv.w, a3);
    }
    g_G2[(i0 + ty) * NT + j0 + tx] = ((a0 + a1) + (a2 + a3)) * LOG2E;

    if (blockIdx.y == 0 && ty == 0) {
        const float4* bf4 = (const float4*)bshf;
        float v0 = 0.f, v1 = 0.f, v2a = 0.f, v3 = 0.f;
#pragma unroll 8
        for (int q = 0; q < NT / 4; q++) {
            float4 bv = brow4[q];
            float4 fv = bf4[q];
            v0 = fmaf(bv.x, fv.x, v0);
            v1 = fmaf(bv.y, fv.y, v1);
            v2a = fmaf(bv.z, fv.z, v2a);
            v3 = fmaf(bv.w, fv.w, v3);
        }
        g_v2[j0 + tx] = ((v0 + v1) + (v2a + v3)) * LOG2E;
        if (blockIdx.x == 0 && tx == 0) {
            float c0 = 0.f;
            for (int k = 0; k < NT; k++) c0 = fmaf(bshf[k], bshf[k], c0);
            g_c2 = c0 * LOG2E;
        }
    }
}

// ---------------- fused per-batch kernel (R10 exact: occ 2, CH 8) -----------------
// a'[r][c] = (w_c*r_r)*G2[r][c] + p2[r]   (log2 domain; per-column const cancels)
// Thread owns columns c0=2cp, c1=2cp+1 (LDG.64 on G2) and rows [64h, 64h+64).
// Pass A: online column max/Z + y=G*r piggyback. Pass B: s_j recomputed via
// symmetry, qcz_c = -mx_c - lg2(Z_c). Pass C: z=G*u. Quadratic-form cosine.
__global__ void __launch_bounds__(NTH, 2) k_fused(const float* __restrict__ req,
                                                  const float* __restrict__ wsdl,
                                                  float* __restrict__ out) {
    __shared__ float2 rp[NT];          // (r, r*v2) per row
    __shared__ float2 bq[NT];          // (w_c, qcz_c) per column
    __shared__ float  us[NT];
    __shared__ float2 mh2[4 * 128], Zh2[4 * 128], yh2[4 * 128];
    __shared__ float2 sh2[4 * 128], zh2[4 * 128];
    __shared__ float red[16 * 6];

    int tid = threadIdx.x;
    int cp = tid & 127;
    int h = tid >> 7;
    int b = blockIdx.x;

    float2 rr = ((const float2*)req)[b * 128 + cp];
    float2 ww = ((const float2*)wsdl)[b * 128 + cp];
    float2 vv = ((const float2*)g_v2)[cp];
    float p20 = rr.x * vv.x, p21 = rr.y * vv.y;
    if (h == 0) {
        rp[2 * cp]     = make_float2(rr.x, p20);
        rp[2 * cp + 1] = make_float2(rr.y, p21);
    }
    __syncthreads();

    const float2* G2v = (const float2*)g_G2;   // row r: G2v[r*128 + cp]
    int rbase = h * RH4;

    // ---- pass A: online column max + Z + y over rows [rbase, rbase+64) ----
    float m0 = -1e30f, m1 = -1e30f, Z0 = 0.f, Z1 = 0.f, y0 = 0.f, y1 = 0.f;
#pragma unroll
    for (int k = 0; k < RH4 / CH; k++) {
        float a0[CH], a1[CH];
        float cm0 = -1e30f, cm1 = -1e30f;
#pragma unroll
        for (int i = 0; i < CH; i++) {
            int r = rbase + k * CH + i;
            float2 g = G2v[r * 128 + cp];
            float2 q = rp[r];                      // broadcast
            a0[i] = fmaf(ww.x * q.x, g.x, q.y);
            a1[i] = fmaf(ww.y * q.x, g.y, q.y);
            y0 = fmaf(g.x, q.x, y0);
            y1 = fmaf(g.y, q.x, y1);
            cm0 = fmaxf(cm0, a0[i]);
            cm1 = fmaxf(cm1, a1[i]);
        }
        float mn0 = fmaxf(m0, cm0), mn1 = fmaxf(m1, cm1);
        Z0 *= fast_exp2(m0 - mn0);   // first chunk: 0 * 2^-huge = 0
        Z1 *= fast_exp2(m1 - mn1);
        m0 = mn0; m1 = mn1;
#pragma unroll
        for (int i = 0; i < CH; i++) {
            Z0 += fast_exp2(a0[i] - m0);
            Z1 += fast_exp2(a1[i] - m1);
        }
    }
    mh2[h * 128 + cp] = make_float2(m0, m1);
    Zh2[h * 128 + cp] = make_float2(Z0, Z1);
    yh2[h * 128 + cp] = make_float2(y0, y1);
    __syncthreads();

    // ---- combine column stats (h==0) -> bq ----
    if (h == 0) {
        float2 ma = mh2[cp], mb = mh2[128 + cp], mc = mh2[256 + cp], md = mh2[384 + cp];
        float mx0 = fmaxf(fmaxf(ma.x, mb.x), fmaxf(mc.x, md.x));
        float mx1 = fmaxf(fmaxf(ma.y, mb.y), fmaxf(mc.y, md.y));
        float2 za = Zh2[cp], zb = Zh2[128 + cp], zc = Zh2[256 + cp], zd = Zh2[384 + cp];
        float Zt0 = za.x * fast_exp2(ma.x - mx0) + zb.x * fast_exp2(mb.x - mx0)
                  + zc.x * fast_exp2(mc.x - mx0) + zd.x * fast_exp2(md.x - mx0);
        float Zt1 = za.y * fast_exp2(ma.y - mx1) + zb.y * fast_exp2(mb.y - mx1)
                  + zc.y * fast_exp2(mc.y - mx1) + zd.y * fast_exp2(md.y - mx1);
        bq[2 * cp]     = make_float2(ww.x, -mx0 - fast_lg2(Zt0));
        bq[2 * cp + 1] = make_float2(ww.y, -mx1 - fast_lg2(Zt1));
    }
    __syncthreads();

    // ---- pass B: s_j over columns cc in [rbase, rbase+64), j = c0,c1 ----
    {
        float s0 = 0.f, s1 = 0.f;
#pragma unroll 16
        for (int cc = rbase; cc < rbase + RH4; cc++) {
            float2 g = G2v[cc * 128 + cp];         // G2[cc][c0], G2[cc][c1]
            float2 t = bq[cc];                     // broadcast
            s0 += fast_exp2(fmaf(t.x * rr.x, g.x, t.y));
            s1 += fast_exp2(fmaf(t.x * rr.y, g.y, t.y));
        }
        sh2[h * 128 + cp] = make_float2(s0, s1);
    }
    __syncthreads();

    // ---- u (h==0 only) ----
    float st0 = 0.f, st1 = 0.f, u0 = 0.f, u1 = 0.f;
    if (h == 0) {
        float2 sa = sh2[cp], sb = sh2[128 + cp], sc = sh2[256 + cp], sd = sh2[384 + cp];
        st0 = ((sa.x + sb.x) + (sc.x + sd.x)) * fast_exp2(p20);
        st1 = ((sa.y + sb.y) + (sc.y + sd.y)) * fast_exp2(p21);
        u0 = st0 * rr.x;
        u1 = st1 * rr.y;
        us[2 * cp] = u0;
        us[2 * cp + 1] = u1;
    }
    __syncthreads();

    // ---- pass C: z = G*u partials ----
    {
        float z0 = 0.f, z1 = 0.f;
#pragma unroll 16
        for (int r = rbase; r < rbase + RH4; r++) {
            float2 g = G2v[r * 128 + cp];
            float uu = us[r];                      // broadcast
            z0 = fmaf(g.x, uu, z0);
            z1 = fmaf(g.y, uu, z1);
        }
        zh2[h * 128 + cp] = make_float2(z0, z1);
    }
    __syncthreads();

    // ---- reductions (h==0 contributes): T0=r.y T1=u.y T2=u.z T3=r.v T4=u.v T5=S --
    float t0 = 0.f, t1 = 0.f, t2 = 0.f, t3 = 0.f, t4 = 0.f, t5 = 0.f;
    if (h == 0) {
        float2 ya = yh2[cp], yb = yh2[128 + cp], yc = yh2[256 + cp], yd = yh2[384 + cp];
        float y0t = (ya.x + yb.x) + (yc.x + yd.x);
        float y1t = (ya.y + yb.y) + (yc.y + yd.y);
        float2 za = zh2[cp], zb = zh2[128 + cp], zc = zh2[256 + cp], zd = zh2[384 + cp];
        float z0t = (za.x + zb.x) + (zc.x + zd.x);
        float z1t = (za.y + zb.y) + (zc.y + zd.y);
        t0 = rr.x * y0t + rr.y * y1t;
        t1 = u0 * y0t + u1 * y1t;
        t2 = u0 * z0t + u1 * z1t;
        t3 = rr.x * vv.x + rr.y * vv.y;
        t4 = u0 * vv.x + u1 * vv.y;
        t5 = st0 + st1;
    }
#pragma unroll
    for (int o = 16; o; o >>= 1) {
        t0 += __shfl_down_sync(0xffffffffu, t0, o);
        t1 += __shfl_down_sync(0xffffffffu, t1, o);
        t2 += __shfl_down_sync(0xffffffffu, t2, o);
        t3 += __shfl_down_sync(0xffffffffu, t3, o);
        t4 += __shfl_down_sync(0xffffffffu, t4, o);
        t5 += __shfl_down_sync(0xffffffffu, t5, o);
    }
    if ((tid & 31) == 0) {
        int w = tid >> 5;
        red[w * 6 + 0] = t0; red[w * 6 + 1] = t1; red[w * 6 + 2] = t2;
        red[w * 6 + 3] = t3; red[w * 6 + 4] = t4; red[w * 6 + 5] = t5;
    }
    __syncthreads();
    if (tid == 0) {
        float T0 = 0, T1 = 0, T2 = 0, T3 = 0, T4 = 0, S = 0;
#pragma unroll
        for (int w = 0; w < 4; w++) {             // only warps 0-3 contribute (h==0)
            T0 += red[w * 6 + 0]; T1 += red[w * 6 + 1]; T2 += red[w * 6 + 2];
            T3 += red[w * 6 + 3]; T4 += red[w * 6 + 4]; S  += red[w * 6 + 5];
        }
        float c_un = g_c2 * INVL2E;
        const float Tf = (float)NT;
        float num = (T1 + S * T3 + Tf * T4) * INVL2E + Tf * S * c_un;
        float n1s = (T0 + 2.0f * Tf * T3) * INVL2E + Tf * Tf * c_un;
        float n2s = (T2 + 2.0f * S * T4) * INVL2E + S * S * c_un;
        float denom = fmaxf(sqrtf(n1s) * sqrtf(n2s), 1e-8f * Tf * Tf);
        out[b] = 3.0f * num / denom;
    }
}

extern "C" void kernel_launch(void* const* d_in, const int* in_sizes, int n_in,
                              void* d_out, int out_size) {
    const float* req  = (const float*)d_in[0];   // [B,T]
    const float* wsdl = (const float*)d_in[1];   // [B,T]
    const float* te   = (const float*)d_in[2];   // [E,T]
    const float* wf   = (const float*)d_in[3];   // [T,E]
    const float* bf   = (const float*)d_in[4];   // [T]
    float* out = (float*)d_out;                  // [B]

    dim3 grd(16, 16);
    k_M<<<grd, 256>>>(te, wf);
    k_Gv<<<grd, 256>>>(bf);
    k_fused<<<NB, NTH>>>(req, wsdl, out);
}